// round 1
// baseline (speedup 1.0000x reference)
#include <cuda_runtime.h>
#include <cuda_bf16.h>

// ---------------------------------------------------------------------------
// GIN forward: 3 x (sum-aggregate + Linear(512,512) + ReLU) + Linear(512,40)
// N = 50000 nodes, E = 400000 edges.
//
// Pipeline per call (all graph-capturable, no allocs):
//   1. zero counts
//   2. histogram of dst
//   3. single-block scan -> CSR offsets (+cursor copy)
//   4. scatter src ids into CSR order
//   5. transpose Wc -> WcT (for coalesced classifier reads)
//   6. 3x [aggregate (gather-sum), sgemm+bias+relu]
//   7. classifier (warp handles 4 rows, WcT L1-resident)
// ---------------------------------------------------------------------------

#define N_NODES 50000
#define DIM     512
#define N_EDGES_MAX 400000
#define NUM_CLASSES 40

// Scratch (device globals; allocation at module load is allowed)
__device__ float4 g_x[N_NODES * (DIM / 4)];   // aggregated input to each Linear
__device__ float4 g_h[N_NODES * (DIM / 4)];   // activations after Linear+ReLU
__device__ int    g_counts[N_NODES + 1];
__device__ int    g_offsets[N_NODES + 1];
__device__ int    g_cursor[N_NODES];
__device__ int    g_esrc[N_EDGES_MAX];
__device__ float  g_WcT[NUM_CLASSES * DIM];

// ---------------------------------------------------------------------------
__global__ void zero_int_kernel(int* p, int n) {
    int i = blockIdx.x * blockDim.x + threadIdx.x;
    if (i < n) p[i] = 0;
}

__global__ void hist_kernel(const int* __restrict__ dst, int* __restrict__ counts, int E) {
    for (int e = blockIdx.x * blockDim.x + threadIdx.x; e < E; e += gridDim.x * blockDim.x)
        atomicAdd(&counts[dst[e]], 1);
}

// Single-block exclusive scan over counts[0..n) -> offsets, cursor; offsets[n]=total
__global__ void scan_kernel(const int* __restrict__ counts, int* __restrict__ offs,
                            int* __restrict__ cursor, int n) {
    __shared__ int sums[1024];
    int t = threadIdx.x;
    const int chunk = (n + 1023) / 1024;
    int beg = t * chunk;
    if (beg > n) beg = n;
    int end = beg + chunk;
    if (end > n) end = n;
    int s = 0;
    for (int i = beg; i < end; i++) s += counts[i];
    int mys = s;
    sums[t] = s;
    __syncthreads();
    for (int off = 1; off < 1024; off <<= 1) {
        int v = (t >= off) ? sums[t - off] : 0;
        __syncthreads();
        sums[t] += v;
        __syncthreads();
    }
    int run = sums[t] - mys;  // exclusive prefix for this thread's chunk
    for (int i = beg; i < end; i++) {
        offs[i] = run;
        cursor[i] = run;
        run += counts[i];
    }
    if (t == 1023) offs[n] = sums[1023];
}

__global__ void scatter_kernel(const int* __restrict__ src, const int* __restrict__ dst,
                               int* __restrict__ cursor, int* __restrict__ esrc, int E) {
    for (int e = blockIdx.x * blockDim.x + threadIdx.x; e < E; e += gridDim.x * blockDim.x) {
        int pos = atomicAdd(&cursor[dst[e]], 1);
        esrc[pos] = src[e];
    }
}

__global__ void transpose_wc_kernel(const float* __restrict__ Wc, float* __restrict__ WcT) {
    int i = blockIdx.x * blockDim.x + threadIdx.x;
    if (i < DIM * NUM_CLASSES) {
        int k = i / NUM_CLASSES, c = i % NUM_CLASSES;
        WcT[c * DIM + k] = Wc[i];
    }
}

// out[node] = in[node] + sum_{e in CSR(node)} in[esrc[e]]   (eps = 0)
__global__ void aggregate_kernel(const float4* __restrict__ in, float4* __restrict__ out,
                                 const int* __restrict__ offs, const int* __restrict__ esrc) {
    int node = blockIdx.x;
    int t = threadIdx.x;  // 0..127, one float4 each (512 floats)
    float4 acc = in[node * 128 + t];
    int beg = offs[node], end = offs[node + 1];
    for (int e = beg; e < end; e++) {
        int s = __ldg(&esrc[e]);
        float4 v = in[s * 128 + t];
        acc.x += v.x; acc.y += v.y; acc.z += v.z; acc.w += v.w;
    }
    out[node * 128 + t] = acc;
}

// C[M,512] = relu(A[M,512] @ B[512,512] + bias)   (classic 128x128x16 SGEMM)
__global__ void __launch_bounds__(256)
gemm_bias_relu_kernel(const float* __restrict__ A, const float* __restrict__ B,
                      const float* __restrict__ bias, float* __restrict__ C, int M) {
    const int K = DIM, N = DIM;
    __shared__ float As[16][136];  // padded to break STS bank conflicts
    __shared__ float Bs[16][128];

    int tid = threadIdx.x;
    int rowBase = blockIdx.y * 128;
    int colBase = blockIdx.x * 128;
    int ty = tid >> 4;   // 0..15 -> 8 rows each
    int tx = tid & 15;   // 0..15 -> 8 cols each

    float acc[8][8];
#pragma unroll
    for (int i = 0; i < 8; i++)
#pragma unroll
        for (int j = 0; j < 8; j++) acc[i][j] = 0.0f;

    for (int k0 = 0; k0 < K; k0 += 16) {
        // Load A tile (128 rows x 16 cols), transposed into As[k][row]
#pragma unroll
        for (int i = 0; i < 2; i++) {
            int idx = tid + i * 256;           // 0..511
            int r = idx >> 2, c4 = idx & 3;    // row 0..127, 4-float group 0..3
            int grow = rowBase + r;
            float4 v = make_float4(0.f, 0.f, 0.f, 0.f);
            if (grow < M) v = *(const float4*)(A + (size_t)grow * K + k0 + c4 * 4);
            As[c4 * 4 + 0][r] = v.x;
            As[c4 * 4 + 1][r] = v.y;
            As[c4 * 4 + 2][r] = v.z;
            As[c4 * 4 + 3][r] = v.w;
        }
        // Load B tile (16 rows x 128 cols)
#pragma unroll
        for (int i = 0; i < 2; i++) {
            int idx = tid + i * 256;
            int kr = idx >> 5, c4 = idx & 31;
            float4 v = *(const float4*)(B + (size_t)(k0 + kr) * N + colBase + c4 * 4);
            *(float4*)(&Bs[kr][c4 * 4]) = v;
        }
        __syncthreads();

#pragma unroll
        for (int kk = 0; kk < 16; kk++) {
            float a[8], b[8];
#pragma unroll
            for (int i = 0; i < 8; i++) a[i] = As[kk][ty * 8 + i];
#pragma unroll
            for (int j = 0; j < 8; j++) b[j] = Bs[kk][tx * 8 + j];
#pragma unroll
            for (int i = 0; i < 8; i++)
#pragma unroll
                for (int j = 0; j < 8; j++) acc[i][j] += a[i] * b[j];
        }
        __syncthreads();
    }

    // Epilogue: bias + relu, guarded stores
#pragma unroll
    for (int i = 0; i < 8; i++) {
        int grow = rowBase + ty * 8 + i;
        if (grow >= M) break;
#pragma unroll
        for (int j = 0; j < 8; j += 4) {
            int gcol = colBase + tx * 8 + j;
            float4 v;
            v.x = acc[i][j + 0] + bias[gcol + 0];
            v.y = acc[i][j + 1] + bias[gcol + 1];
            v.z = acc[i][j + 2] + bias[gcol + 2];
            v.w = acc[i][j + 3] + bias[gcol + 3];
            v.x = fmaxf(v.x, 0.f); v.y = fmaxf(v.y, 0.f);
            v.z = fmaxf(v.z, 0.f); v.w = fmaxf(v.w, 0.f);
            *(float4*)(C + (size_t)grow * N + gcol) = v;
        }
    }
}

// out[M,40] = X[M,512] @ Wc + bc.  Warp handles 4 rows; WcT is L1-resident (80KB).
__global__ void __launch_bounds__(256)
classifier_kernel(const float* __restrict__ X, const float* __restrict__ WcT,
                  const float* __restrict__ bc, float* __restrict__ out, int M) {
    int warp = (blockIdx.x * blockDim.x + threadIdx.x) >> 5;
    int lane = threadIdx.x & 31;
    int row0 = warp * 4;
    if (row0 >= M) return;  // M divisible by 4

    float x0[16], x1[16], x2[16], x3[16];
    const float* X0 = X + (size_t)row0 * DIM;
#pragma unroll
    for (int j = 0; j < 16; j++) {
        int k = j * 32 + lane;
        x0[j] = X0[k];
        x1[j] = X0[DIM + k];
        x2[j] = X0[2 * DIM + k];
        x3[j] = X0[3 * DIM + k];
    }

    for (int c = 0; c < NUM_CLASSES; c++) {
        const float* w = WcT + c * DIM;
        float s0 = 0.f, s1 = 0.f, s2 = 0.f, s3 = 0.f;
#pragma unroll
        for (int j = 0; j < 16; j++) {
            float wv = __ldg(&w[j * 32 + lane]);
            s0 += x0[j] * wv;
            s1 += x1[j] * wv;
            s2 += x2[j] * wv;
            s3 += x3[j] * wv;
        }
#pragma unroll
        for (int o = 16; o > 0; o >>= 1) {
            s0 += __shfl_xor_sync(0xffffffffu, s0, o);
            s1 += __shfl_xor_sync(0xffffffffu, s1, o);
            s2 += __shfl_xor_sync(0xffffffffu, s2, o);
            s3 += __shfl_xor_sync(0xffffffffu, s3, o);
        }
        if (lane == 0) {
            float b = bc[c];
            out[(size_t)(row0 + 0) * NUM_CLASSES + c] = s0 + b;
            out[(size_t)(row0 + 1) * NUM_CLASSES + c] = s1 + b;
            out[(size_t)(row0 + 2) * NUM_CLASSES + c] = s2 + b;
            out[(size_t)(row0 + 3) * NUM_CLASSES + c] = s3 + b;
        }
    }
}

// ---------------------------------------------------------------------------
extern "C" void kernel_launch(void* const* d_in, const int* in_sizes, int n_in,
                              void* d_out, int out_size) {
    const float* feat = (const float*)d_in[0];
    const int*   src  = (const int*)d_in[1];
    const int*   dst  = (const int*)d_in[2];
    const float* W0 = (const float*)d_in[3];
    const float* b0 = (const float*)d_in[4];
    const float* W1 = (const float*)d_in[5];
    const float* b1 = (const float*)d_in[6];
    const float* W2 = (const float*)d_in[7];
    const float* b2 = (const float*)d_in[8];
    const float* Wc = (const float*)d_in[9];
    const float* bc = (const float*)d_in[10];
    int E = in_sizes[1];

    float4* px;  float4* ph;
    int *pcounts, *poffs, *pcursor, *pesrc;
    float* pWcT;
    cudaGetSymbolAddress((void**)&px,      g_x);
    cudaGetSymbolAddress((void**)&ph,      g_h);
    cudaGetSymbolAddress((void**)&pcounts, g_counts);
    cudaGetSymbolAddress((void**)&poffs,   g_offsets);
    cudaGetSymbolAddress((void**)&pcursor, g_cursor);
    cudaGetSymbolAddress((void**)&pesrc,   g_esrc);
    cudaGetSymbolAddress((void**)&pWcT,    g_WcT);

    // CSR build
    zero_int_kernel<<<(N_NODES + 1 + 255) / 256, 256>>>(pcounts, N_NODES + 1);
    hist_kernel<<<512, 256>>>(dst, pcounts, E);
    scan_kernel<<<1, 1024>>>(pcounts, poffs, pcursor, N_NODES);
    scatter_kernel<<<512, 256>>>(src, dst, pcursor, pesrc, E);
    transpose_wc_kernel<<<(DIM * NUM_CLASSES + 255) / 256, 256>>>(Wc, pWcT);

    dim3 ggrid(DIM / 128, (N_NODES + 127) / 128);

    // Layer 1
    aggregate_kernel<<<N_NODES, 128>>>((const float4*)feat, px, poffs, pesrc);
    gemm_bias_relu_kernel<<<ggrid, 256>>>((const float*)px, W0, b0, (float*)ph, N_NODES);
    // Layer 2
    aggregate_kernel<<<N_NODES, 128>>>((const float4*)ph, px, poffs, pesrc);
    gemm_bias_relu_kernel<<<ggrid, 256>>>((const float*)px, W1, b1, (float*)ph, N_NODES);
    // Layer 3
    aggregate_kernel<<<N_NODES, 128>>>((const float4*)ph, px, poffs, pesrc);
    gemm_bias_relu_kernel<<<ggrid, 256>>>((const float*)px, W2, b2, (float*)ph, N_NODES);

    // Classifier
    classifier_kernel<<<(N_NODES / 4 * 32 + 255) / 256, 256>>>(
        (const float*)ph, pWcT, bc, (float*)d_out, N_NODES);
}

// round 3
// speedup vs baseline: 1.4809x; 1.4809x over previous
#include <cuda_runtime.h>
#include <cuda_bf16.h>
#include <cstdint>

// ---------------------------------------------------------------------------
// GIN forward: 3 x (sum-aggregate + Linear(512,512) + ReLU) + Linear(512,40)
// GEMMs on tensor cores via mma.sync.m16n8k8 tf32 (sm_103 harness emits
// .target sm_103 w/o 'a' -> tcgen05 unavailable; legacy HMMA path is not).
// ---------------------------------------------------------------------------

#define N_NODES 50000
#define DIM     512
#define N_EDGES_MAX 400000
#define NUM_CLASSES 40

__device__ float4 g_x[N_NODES * (DIM / 4)];
__device__ float4 g_h[N_NODES * (DIM / 4)];
__device__ int    g_counts[N_NODES + 1];
__device__ int    g_offsets[N_NODES + 1];
__device__ int    g_cursor[N_NODES];
__device__ int    g_esrc[N_EDGES_MAX];
__device__ float  g_WcT[NUM_CLASSES * DIM];
__device__ float  g_WT[3 * DIM * DIM];   // weights transposed to [N, K] K-major

// ------------------------- CSR build ---------------------------------------
__global__ void zero_int_kernel(int* p, int n) {
    int i = blockIdx.x * blockDim.x + threadIdx.x;
    if (i < n) p[i] = 0;
}

__global__ void hist_kernel(const int* __restrict__ dst, int* __restrict__ counts, int E) {
    for (int e = blockIdx.x * blockDim.x + threadIdx.x; e < E; e += gridDim.x * blockDim.x)
        atomicAdd(&counts[dst[e]], 1);
}

__global__ void scan_kernel(const int* __restrict__ counts, int* __restrict__ offs,
                            int* __restrict__ cursor, int n) {
    __shared__ int sums[1024];
    int t = threadIdx.x;
    const int chunk = (n + 1023) / 1024;
    int beg = t * chunk; if (beg > n) beg = n;
    int end = beg + chunk; if (end > n) end = n;
    int s = 0;
    for (int i = beg; i < end; i++) s += counts[i];
    int mys = s;
    sums[t] = s;
    __syncthreads();
    for (int off = 1; off < 1024; off <<= 1) {
        int v = (t >= off) ? sums[t - off] : 0;
        __syncthreads();
        sums[t] += v;
        __syncthreads();
    }
    int run = sums[t] - mys;
    for (int i = beg; i < end; i++) {
        offs[i] = run; cursor[i] = run; run += counts[i];
    }
    if (t == 1023) offs[n] = sums[1023];
}

__global__ void scatter_kernel(const int* __restrict__ src, const int* __restrict__ dst,
                               int* __restrict__ cursor, int* __restrict__ esrc, int E) {
    for (int e = blockIdx.x * blockDim.x + threadIdx.x; e < E; e += gridDim.x * blockDim.x) {
        int pos = atomicAdd(&cursor[dst[e]], 1);
        esrc[pos] = src[e];
    }
}

__global__ void transpose_wc_kernel(const float* __restrict__ Wc, float* __restrict__ WcT) {
    int i = blockIdx.x * blockDim.x + threadIdx.x;
    if (i < DIM * NUM_CLASSES) {
        int k = i / NUM_CLASSES, c = i % NUM_CLASSES;
        WcT[c * DIM + k] = Wc[i];
    }
}

// W [K=512, N=512] row-major  ->  WT [N=512, K=512] row-major
__global__ void transpose512_kernel(const float* __restrict__ W, float* __restrict__ WT) {
    __shared__ float t[32][33];
    int bx = blockIdx.x * 32, by = blockIdx.y * 32;
#pragma unroll
    for (int i = 0; i < 32; i += 8)
        t[threadIdx.y + i][threadIdx.x] = W[(by + threadIdx.y + i) * DIM + bx + threadIdx.x];
    __syncthreads();
#pragma unroll
    for (int i = 0; i < 32; i += 8)
        WT[(bx + threadIdx.y + i) * DIM + by + threadIdx.x] = t[threadIdx.x][threadIdx.y + i];
}

// ------------------------- aggregation -------------------------------------
__global__ void aggregate_kernel(const float4* __restrict__ in, float4* __restrict__ out,
                                 const int* __restrict__ offs, const int* __restrict__ esrc) {
    int node = blockIdx.x;
    int t = threadIdx.x;
    float4 acc = in[node * 128 + t];
    int beg = offs[node], end = offs[node + 1];
    for (int e = beg; e < end; e++) {
        int s = __ldg(&esrc[e]);
        float4 v = in[s * 128 + t];
        acc.x += v.x; acc.y += v.y; acc.z += v.z; acc.w += v.w;
    }
    out[node * 128 + t] = acc;
}

// ------------------------- tf32 mma.sync GEMM ------------------------------
__device__ __forceinline__ uint32_t f2tf32(float f) {
    uint32_t u;
    asm("cvt.rna.tf32.f32 %0, %1;" : "=r"(u) : "f"(f));
    return u;
}

__device__ __forceinline__ void mma_tf32(float c[4], const uint32_t a[4], const uint32_t b[2]) {
    asm volatile(
        "mma.sync.aligned.m16n8k8.row.col.f32.tf32.tf32.f32 "
        "{%0,%1,%2,%3}, {%4,%5,%6,%7}, {%8,%9}, {%0,%1,%2,%3};"
        : "+f"(c[0]), "+f"(c[1]), "+f"(c[2]), "+f"(c[3])
        : "r"(a[0]), "r"(a[1]), "r"(a[2]), "r"(a[3]), "r"(b[0]), "r"(b[1]));
}

#define GS 136                      // SMEM k-row stride in floats (conflict-free)
#define STAGE_FLOATS (2 * 32 * GS)  // A tile + B tile, one stage

// C[M,512] = relu(A[M,512] @ WT^T + bias); WT is [N=512, K=512] row-major.
// CTA tile 128x128, 8 warps (4 along M x 2 along N), warptile 32x64.
// K-chunks of 32, double-buffered SMEM, SMEM layout [k][m] stride GS.
__global__ void __launch_bounds__(256)
gemm_mma_kernel(const float* __restrict__ A, const float* __restrict__ BT,
                const float* __restrict__ bias, float* __restrict__ C, int M) {
    extern __shared__ float sm[];   // [2][2][32][GS]

    int tid = threadIdx.x;
    int lane = tid & 31, wid = tid >> 5;
    int warpM = wid & 3;            // 0..3 -> 32-row group
    int warpN = wid >> 2;           // 0..1 -> 64-col group
    int gid = lane >> 2;            // 0..7
    int tig = lane & 3;             // 0..3
    int rowBase = blockIdx.y * 128;
    int colBase = blockIdx.x * 128;

    // Global->SMEM mapping: thread owns one tile-row, 4 float4 groups per chunk
    int lrow = tid & 127;
    int g0 = tid >> 7;              // 0..1
    const float* Aptr = A + (size_t)(rowBase + lrow) * DIM;
    const float* Bptr = BT + (size_t)(colBase + lrow) * DIM;
    bool arow_ok = (rowBase + lrow) < M;

    float acc[2][8][4];
#pragma unroll
    for (int mt = 0; mt < 2; mt++)
#pragma unroll
        for (int nt = 0; nt < 8; nt++)
#pragma unroll
            for (int c = 0; c < 4; c++) acc[mt][nt][c] = 0.f;

    float4 ra[4], rb[4];
#pragma unroll
    for (int j = 0; j < 4; j++) {
        int g = g0 + 2 * j;
        ra[j] = arow_ok ? *(const float4*)(Aptr + g * 4) : make_float4(0.f, 0.f, 0.f, 0.f);
        rb[j] = *(const float4*)(Bptr + g * 4);
    }

    for (int kt = 0; kt < 16; kt++) {
        float* sA = sm + (kt & 1) * STAGE_FLOATS;
        float* sB = sA + 32 * GS;
        // Store chunk (converted to tf32), transposed to [k][m]
#pragma unroll
        for (int j = 0; j < 4; j++) {
            int g = g0 + 2 * j;
            sA[(g * 4 + 0) * GS + lrow] = __uint_as_float(f2tf32(ra[j].x));
            sA[(g * 4 + 1) * GS + lrow] = __uint_as_float(f2tf32(ra[j].y));
            sA[(g * 4 + 2) * GS + lrow] = __uint_as_float(f2tf32(ra[j].z));
            sA[(g * 4 + 3) * GS + lrow] = __uint_as_float(f2tf32(ra[j].w));
            sB[(g * 4 + 0) * GS + lrow] = __uint_as_float(f2tf32(rb[j].x));
            sB[(g * 4 + 1) * GS + lrow] = __uint_as_float(f2tf32(rb[j].y));
            sB[(g * 4 + 2) * GS + lrow] = __uint_as_float(f2tf32(rb[j].z));
            sB[(g * 4 + 3) * GS + lrow] = __uint_as_float(f2tf32(rb[j].w));
        }
        __syncthreads();
        // Prefetch next chunk
        if (kt < 15) {
            int k0 = (kt + 1) * 32;
#pragma unroll
            for (int j = 0; j < 4; j++) {
                int g = g0 + 2 * j;
                ra[j] = arow_ok ? *(const float4*)(Aptr + k0 + g * 4)
                                : make_float4(0.f, 0.f, 0.f, 0.f);
                rb[j] = *(const float4*)(Bptr + k0 + g * 4);
            }
        }
        // Compute: 4 k-steps of 8
#pragma unroll
        for (int ks = 0; ks < 4; ks++) {
            int kb = ks * 8;
            uint32_t af[2][4];
#pragma unroll
            for (int mt = 0; mt < 2; mt++) {
                int mrow = warpM * 32 + mt * 16 + gid;
                af[mt][0] = __float_as_uint(sA[(kb + tig) * GS + mrow]);
                af[mt][1] = __float_as_uint(sA[(kb + tig) * GS + mrow + 8]);
                af[mt][2] = __float_as_uint(sA[(kb + 4 + tig) * GS + mrow]);
                af[mt][3] = __float_as_uint(sA[(kb + 4 + tig) * GS + mrow + 8]);
            }
            uint32_t bf[8][2];
#pragma unroll
            for (int nt = 0; nt < 8; nt++) {
                int ncol = warpN * 64 + nt * 8 + gid;
                bf[nt][0] = __float_as_uint(sB[(kb + tig) * GS + ncol]);
                bf[nt][1] = __float_as_uint(sB[(kb + 4 + tig) * GS + ncol]);
            }
#pragma unroll
            for (int mt = 0; mt < 2; mt++)
#pragma unroll
                for (int nt = 0; nt < 8; nt++)
                    mma_tf32(acc[mt][nt], af[mt], bf[nt]);
        }
        __syncthreads();
    }

    // Epilogue: bias + relu
#pragma unroll
    for (int mt = 0; mt < 2; mt++) {
        int r0 = rowBase + warpM * 32 + mt * 16 + gid;
        int r1 = r0 + 8;
#pragma unroll
        for (int nt = 0; nt < 8; nt++) {
            int col = colBase + warpN * 64 + nt * 8 + 2 * tig;
            float bx = bias[col], by = bias[col + 1];
            if (r0 < M) {
                float2 v;
                v.x = fmaxf(acc[mt][nt][0] + bx, 0.f);
                v.y = fmaxf(acc[mt][nt][1] + by, 0.f);
                *(float2*)(C + (size_t)r0 * DIM + col) = v;
            }
            if (r1 < M) {
                float2 v;
                v.x = fmaxf(acc[mt][nt][2] + bx, 0.f);
                v.y = fmaxf(acc[mt][nt][3] + by, 0.f);
                *(float2*)(C + (size_t)r1 * DIM + col) = v;
            }
        }
    }
}

// ------------------------- classifier --------------------------------------
__global__ void __launch_bounds__(256)
classifier_kernel(const float* __restrict__ X, const float* __restrict__ WcT,
                  const float* __restrict__ bc, float* __restrict__ out, int M) {
    int warp = (blockIdx.x * blockDim.x + threadIdx.x) >> 5;
    int lane = threadIdx.x & 31;
    int row0 = warp * 4;
    if (row0 >= M) return;

    float x0[16], x1[16], x2[16], x3[16];
    const float* X0 = X + (size_t)row0 * DIM;
#pragma unroll
    for (int j = 0; j < 16; j++) {
        int k = j * 32 + lane;
        x0[j] = X0[k];
        x1[j] = X0[DIM + k];
        x2[j] = X0[2 * DIM + k];
        x3[j] = X0[3 * DIM + k];
    }

    for (int c = 0; c < NUM_CLASSES; c++) {
        const float* w = WcT + c * DIM;
        float s0 = 0.f, s1 = 0.f, s2 = 0.f, s3 = 0.f;
#pragma unroll
        for (int j = 0; j < 16; j++) {
            float wv = __ldg(&w[j * 32 + lane]);
            s0 += x0[j] * wv; s1 += x1[j] * wv;
            s2 += x2[j] * wv; s3 += x3[j] * wv;
        }
#pragma unroll
        for (int o = 16; o > 0; o >>= 1) {
            s0 += __shfl_xor_sync(0xffffffffu, s0, o);
            s1 += __shfl_xor_sync(0xffffffffu, s1, o);
            s2 += __shfl_xor_sync(0xffffffffu, s2, o);
            s3 += __shfl_xor_sync(0xffffffffu, s3, o);
        }
        if (lane == 0) {
            float b = bc[c];
            out[(size_t)(row0 + 0) * NUM_CLASSES + c] = s0 + b;
            out[(size_t)(row0 + 1) * NUM_CLASSES + c] = s1 + b;
            out[(size_t)(row0 + 2) * NUM_CLASSES + c] = s2 + b;
            out[(size_t)(row0 + 3) * NUM_CLASSES + c] = s3 + b;
        }
    }
}

// ---------------------------------------------------------------------------
extern "C" void kernel_launch(void* const* d_in, const int* in_sizes, int n_in,
                              void* d_out, int out_size) {
    const float* feat = (const float*)d_in[0];
    const int*   src  = (const int*)d_in[1];
    const int*   dst  = (const int*)d_in[2];
    const float* W0 = (const float*)d_in[3];
    const float* b0 = (const float*)d_in[4];
    const float* W1 = (const float*)d_in[5];
    const float* b1 = (const float*)d_in[6];
    const float* W2 = (const float*)d_in[7];
    const float* b2 = (const float*)d_in[8];
    const float* Wc = (const float*)d_in[9];
    const float* bc = (const float*)d_in[10];
    int E = in_sizes[1];

    float4* px;  float4* ph;
    int *pcounts, *poffs, *pcursor, *pesrc;
    float *pWcT, *pWT;
    cudaGetSymbolAddress((void**)&px,      g_x);
    cudaGetSymbolAddress((void**)&ph,      g_h);
    cudaGetSymbolAddress((void**)&pcounts, g_counts);
    cudaGetSymbolAddress((void**)&poffs,   g_offsets);
    cudaGetSymbolAddress((void**)&pcursor, g_cursor);
    cudaGetSymbolAddress((void**)&pesrc,   g_esrc);
    cudaGetSymbolAddress((void**)&pWcT,    g_WcT);
    cudaGetSymbolAddress((void**)&pWT,     g_WT);

    const int GSMEM = 2 * STAGE_FLOATS * (int)sizeof(float);   // 69632 B
    static int smem_set = 0;
    if (!smem_set) {
        cudaFuncSetAttribute(gemm_mma_kernel,
                             cudaFuncAttributeMaxDynamicSharedMemorySize, GSMEM);
        smem_set = 1;
    }

    // CSR build + weight prep
    zero_int_kernel<<<(N_NODES + 1 + 255) / 256, 256>>>(pcounts, N_NODES + 1);
    hist_kernel<<<512, 256>>>(dst, pcounts, E);
    scan_kernel<<<1, 1024>>>(pcounts, poffs, pcursor, N_NODES);
    scatter_kernel<<<512, 256>>>(src, dst, pcursor, pesrc, E);
    transpose_wc_kernel<<<(DIM * NUM_CLASSES + 255) / 256, 256>>>(Wc, pWcT);
    dim3 tgrid(16, 16), tblk(32, 8);
    transpose512_kernel<<<tgrid, tblk>>>(W0, pWT + 0 * DIM * DIM);
    transpose512_kernel<<<tgrid, tblk>>>(W1, pWT + 1 * DIM * DIM);
    transpose512_kernel<<<tgrid, tblk>>>(W2, pWT + 2 * DIM * DIM);

    dim3 ggrid(DIM / 128, (N_NODES + 127) / 128);

    aggregate_kernel<<<N_NODES, 128>>>((const float4*)feat, px, poffs, pesrc);
    gemm_mma_kernel<<<ggrid, 256, GSMEM>>>((const float*)px, pWT + 0 * DIM * DIM, b0, (float*)ph, N_NODES);

    aggregate_kernel<<<N_NODES, 128>>>(ph, px, poffs, pesrc);
    gemm_mma_kernel<<<ggrid, 256, GSMEM>>>((const float*)px, pWT + 1 * DIM * DIM, b1, (float*)ph, N_NODES);

    aggregate_kernel<<<N_NODES, 128>>>(ph, px, poffs, pesrc);
    gemm_mma_kernel<<<ggrid, 256, GSMEM>>>((const float*)px, pWT + 2 * DIM * DIM, b2, (float*)ph, N_NODES);

    classifier_kernel<<<(N_NODES / 4 * 32 + 255) / 256, 256>>>(
        (const float*)ph, pWcT, bc, (float*)d_out, N_NODES);
}

// round 7
// speedup vs baseline: 1.7914x; 1.2096x over previous
#include <cuda_runtime.h>
#include <cuda_bf16.h>
#include <cstdint>

// ---------------------------------------------------------------------------
// GIN forward: 3 x (sum-aggregate + Linear(512,512) + ReLU) + Linear(512,40)
// - Aggregation: L2-tiled gather (4 column tiles of 25MB -> L2-resident)
// - GEMM: mma.sync tf32, cp.async double-buffered tiles, operands pre-rounded
// ---------------------------------------------------------------------------

#define N_NODES 50000
#define DIM     512
#define N_EDGES_MAX 400000
#define NUM_CLASSES 40

__device__ float4 g_x[N_NODES * (DIM / 4)];
__device__ float4 g_h[N_NODES * (DIM / 4)];
__device__ int    g_counts[N_NODES + 1];
__device__ int    g_offsets[N_NODES + 1];
__device__ int    g_cursor[N_NODES];
__device__ int    g_esrc[N_EDGES_MAX];
__device__ float  g_WcT[NUM_CLASSES * DIM];
__device__ float  g_WT[3 * DIM * DIM];   // weights [N,K] K-major, tf32-rounded

// ------------------------- helpers -----------------------------------------
__device__ __forceinline__ uint32_t f2tf32(float f) {
    uint32_t u;
    asm("cvt.rna.tf32.f32 %0, %1;" : "=r"(u) : "f"(f));
    return u;
}
__device__ __forceinline__ float4 round_tf32_f4(float4 v) {
    v.x = __uint_as_float(f2tf32(v.x));
    v.y = __uint_as_float(f2tf32(v.y));
    v.z = __uint_as_float(f2tf32(v.z));
    v.w = __uint_as_float(f2tf32(v.w));
    return v;
}
__device__ __forceinline__ uint32_t smem_u32(const void* p) {
    uint32_t a;
    asm("{ .reg .u64 t; cvta.to.shared.u64 t, %1; cvt.u32.u64 %0, t; }" : "=r"(a) : "l"(p));
    return a;
}
__device__ __forceinline__ void cp16(uint32_t saddr, const void* gaddr, int src_bytes) {
    asm volatile("cp.async.cg.shared.global [%0], [%1], 16, %2;"
                 :: "r"(saddr), "l"(gaddr), "r"(src_bytes) : "memory");
}
__device__ __forceinline__ void cp_commit() {
    asm volatile("cp.async.commit_group;" ::: "memory");
}
template <int N>
__device__ __forceinline__ void cp_wait() {
    asm volatile("cp.async.wait_group %0;" :: "n"(N) : "memory");
}
__device__ __forceinline__ void mma_tf32(float c[4], const uint32_t a[4], const uint32_t b[2]) {
    asm volatile(
        "mma.sync.aligned.m16n8k8.row.col.f32.tf32.tf32.f32 "
        "{%0,%1,%2,%3}, {%4,%5,%6,%7}, {%8,%9}, {%0,%1,%2,%3};"
        : "+f"(c[0]), "+f"(c[1]), "+f"(c[2]), "+f"(c[3])
        : "r"(a[0]), "r"(a[1]), "r"(a[2]), "r"(a[3]), "r"(b[0]), "r"(b[1]));
}

// ------------------------- CSR build ---------------------------------------
__global__ void zero_int_kernel(int* p, int n) {
    int i = blockIdx.x * blockDim.x + threadIdx.x;
    if (i < n) p[i] = 0;
}

__global__ void hist_kernel(const int* __restrict__ dst, int* __restrict__ counts, int E) {
    for (int e = blockIdx.x * blockDim.x + threadIdx.x; e < E; e += gridDim.x * blockDim.x)
        atomicAdd(&counts[dst[e]], 1);
}

__global__ void scan_kernel(const int* __restrict__ counts, int* __restrict__ offs,
                            int* __restrict__ cursor, int n) {
    __shared__ int sums[1024];
    int t = threadIdx.x;
    const int chunk = (n + 1023) / 1024;
    int beg = t * chunk; if (beg > n) beg = n;
    int end = beg + chunk; if (end > n) end = n;
    int s = 0;
    for (int i = beg; i < end; i++) s += counts[i];
    int mys = s;
    sums[t] = s;
    __syncthreads();
    for (int off = 1; off < 1024; off <<= 1) {
        int v = (t >= off) ? sums[t - off] : 0;
        __syncthreads();
        sums[t] += v;
        __syncthreads();
    }
    int run = sums[t] - mys;
    for (int i = beg; i < end; i++) {
        offs[i] = run; cursor[i] = run; run += counts[i];
    }
    if (t == 1023) offs[n] = sums[1023];
}

__global__ void scatter_kernel(const int* __restrict__ src, const int* __restrict__ dst,
                               int* __restrict__ cursor, int* __restrict__ esrc, int E) {
    for (int e = blockIdx.x * blockDim.x + threadIdx.x; e < E; e += gridDim.x * blockDim.x) {
        int pos = atomicAdd(&cursor[dst[e]], 1);
        esrc[pos] = src[e];
    }
}

__global__ void transpose_wc_kernel(const float* __restrict__ Wc, float* __restrict__ WcT) {
    int i = blockIdx.x * blockDim.x + threadIdx.x;
    if (i < DIM * NUM_CLASSES) {
        int k = i / NUM_CLASSES, c = i % NUM_CLASSES;
        WcT[c * DIM + k] = Wc[i];
    }
}

// W [K,N] row-major -> WT [N,K] row-major, rounded to tf32
__global__ void transpose512_kernel(const float* __restrict__ W, float* __restrict__ WT) {
    __shared__ float t[32][33];
    int bx = blockIdx.x * 32, by = blockIdx.y * 32;
#pragma unroll
    for (int i = 0; i < 32; i += 8)
        t[threadIdx.y + i][threadIdx.x] = W[(by + threadIdx.y + i) * DIM + bx + threadIdx.x];
    __syncthreads();
#pragma unroll
    for (int i = 0; i < 32; i += 8) {
        float v = t[threadIdx.x][threadIdx.y + i];
        WT[(bx + threadIdx.y + i) * DIM + by + threadIdx.x] = __uint_as_float(f2tf32(v));
    }
}

// ------------------------- L2-tiled aggregation -----------------------------
// One warp per node, one 128-float column tile per launch (slice = 25MB -> L2).
// out = tf32_round(in[node] + sum_{e} in[esrc[e]]) on the tile's columns.
__global__ void __launch_bounds__(128)
agg_tile_kernel(const float4* __restrict__ in, float4* __restrict__ out,
                const int* __restrict__ offs, const int* __restrict__ esrc, int tile) {
    int warp = threadIdx.x >> 5;
    int lane = threadIdx.x & 31;
    int node = blockIdx.x * 4 + warp;
    if (node >= N_NODES) return;
    int col = tile * 32 + lane;            // float4 column within 128-float4 row

    float4 acc = in[(size_t)node * 128 + col];
    int e = offs[node], end = offs[node + 1];
    for (; e + 1 < end; e += 2) {
        int s0 = __ldg(&esrc[e]);
        int s1 = __ldg(&esrc[e + 1]);
        float4 v0 = in[(size_t)s0 * 128 + col];
        float4 v1 = in[(size_t)s1 * 128 + col];
        acc.x += v0.x + v1.x; acc.y += v0.y + v1.y;
        acc.z += v0.z + v1.z; acc.w += v0.w + v1.w;
    }
    if (e < end) {
        int s0 = __ldg(&esrc[e]);
        float4 v0 = in[(size_t)s0 * 128 + col];
        acc.x += v0.x; acc.y += v0.y; acc.z += v0.z; acc.w += v0.w;
    }
    out[(size_t)node * 128 + col] = round_tf32_f4(acc);
}

// ------------------------- tf32 mma.sync GEMM (cp.async) --------------------
#define STR 36                           // SMEM row stride in floats
#define TILE_FLOATS (128 * STR)          // one operand tile
#define STAGE_FLOATS (2 * TILE_FLOATS)   // A + B

// C[M,512] = relu(A @ WT^T + bias); A,WT already tf32-rounded.
// CTA 128x128, 8 warps (4 M x 2 N), warptile 32x64, K-chunks 32, 2 stages.
__global__ void __launch_bounds__(256)
gemm_mma_kernel(const float* __restrict__ A, const float* __restrict__ BT,
                const float* __restrict__ bias, float* __restrict__ C, int M) {
    extern __shared__ float sm[];   // [2][A:128*STR | B:128*STR]

    int tid = threadIdx.x;
    int lane = tid & 31, wid = tid >> 5;
    int warpM = wid & 3, warpN = wid >> 2;
    int gid = lane >> 2, tig = lane & 3;
    int rowBase = blockIdx.y * 128;
    int colBase = blockIdx.x * 128;

    // cp.async mapping: thread -> (row, half); 4 x 16B chunks per operand
    int lrow = tid >> 1;          // 0..127
    int half = tid & 1;           // 0..1 (which 64B half of the 128B row-chunk)
    const float* Aptr = A + (size_t)(rowBase + lrow) * DIM + half * 16;
    const float* Bptr = BT + (size_t)(colBase + lrow) * DIM + half * 16;
    int a_bytes = ((rowBase + lrow) < M) ? 16 : 0;

    uint32_t smem_base = smem_u32(sm);
    uint32_t sA_st = smem_base + (lrow * STR + half * 16) * 4;
    uint32_t sB_st = sA_st + TILE_FLOATS * 4;

    float acc[2][8][4];
#pragma unroll
    for (int mt = 0; mt < 2; mt++)
#pragma unroll
        for (int nt = 0; nt < 8; nt++)
#pragma unroll
            for (int c = 0; c < 4; c++) acc[mt][nt][c] = 0.f;

    // prologue: stage 0 (k0 = 0)
#pragma unroll
    for (int i = 0; i < 4; i++) {
        cp16(sA_st + i * 16, Aptr + i * 4, a_bytes);
        cp16(sB_st + i * 16, Bptr + i * 4, 16);
    }
    cp_commit();

    for (int kt = 0; kt < 16; kt++) {
        if (kt < 15) {
            int k0 = (kt + 1) * 32;
            uint32_t off = ((kt + 1) & 1) * STAGE_FLOATS * 4;
#pragma unroll
            for (int i = 0; i < 4; i++) {
                cp16(sA_st + off + i * 16, Aptr + k0 + i * 4, a_bytes);
                cp16(sB_st + off + i * 16, Bptr + k0 + i * 4, 16);
            }
            cp_commit();
            cp_wait<1>();
        } else {
            cp_wait<0>();
        }
        __syncthreads();

        const float* sA = sm + (kt & 1) * STAGE_FLOATS;
        const float* sB = sA + TILE_FLOATS;
#pragma unroll
        for (int ks = 0; ks < 4; ks++) {
            int kb = ks * 8;
            uint32_t af[2][4];
#pragma unroll
            for (int mt = 0; mt < 2; mt++) {
                int mrow = warpM * 32 + mt * 16 + gid;
                af[mt][0] = __float_as_uint(sA[mrow * STR + kb + tig]);
                af[mt][1] = __float_as_uint(sA[(mrow + 8) * STR + kb + tig]);
                af[mt][2] = __float_as_uint(sA[mrow * STR + kb + 4 + tig]);
                af[mt][3] = __float_as_uint(sA[(mrow + 8) * STR + kb + 4 + tig]);
            }
            uint32_t bf[8][2];
#pragma unroll
            for (int nt = 0; nt < 8; nt++) {
                int ncol = warpN * 64 + nt * 8 + gid;
                bf[nt][0] = __float_as_uint(sB[ncol * STR + kb + tig]);
                bf[nt][1] = __float_as_uint(sB[ncol * STR + kb + 4 + tig]);
            }
#pragma unroll
            for (int mt = 0; mt < 2; mt++)
#pragma unroll
                for (int nt = 0; nt < 8; nt++)
                    mma_tf32(acc[mt][nt], af[mt], bf[nt]);
        }
        __syncthreads();
    }

    // Epilogue: bias + relu
#pragma unroll
    for (int mt = 0; mt < 2; mt++) {
        int r0 = rowBase + warpM * 32 + mt * 16 + gid;
        int r1 = r0 + 8;
#pragma unroll
        for (int nt = 0; nt < 8; nt++) {
            int col = colBase + warpN * 64 + nt * 8 + 2 * tig;
            float bx = bias[col], by = bias[col + 1];
            if (r0 < M) {
                float2 v;
                v.x = fmaxf(acc[mt][nt][0] + bx, 0.f);
                v.y = fmaxf(acc[mt][nt][1] + by, 0.f);
                *(float2*)(C + (size_t)r0 * DIM + col) = v;
            }
            if (r1 < M) {
                float2 v;
                v.x = fmaxf(acc[mt][nt][2] + bx, 0.f);
                v.y = fmaxf(acc[mt][nt][3] + by, 0.f);
                *(float2*)(C + (size_t)r1 * DIM + col) = v;
            }
        }
    }
}

// ------------------------- classifier --------------------------------------
__global__ void __launch_bounds__(256)
classifier_kernel(const float* __restrict__ X, const float* __restrict__ WcT,
                  const float* __restrict__ bc, float* __restrict__ out, int M) {
    int warp = (blockIdx.x * blockDim.x + threadIdx.x) >> 5;
    int lane = threadIdx.x & 31;
    int row0 = warp * 4;
    if (row0 >= M) return;

    float x0[16], x1[16], x2[16], x3[16];
    const float* X0 = X + (size_t)row0 * DIM;
#pragma unroll
    for (int j = 0; j < 16; j++) {
        int k = j * 32 + lane;
        x0[j] = X0[k];
        x1[j] = X0[DIM + k];
        x2[j] = X0[2 * DIM + k];
        x3[j] = X0[3 * DIM + k];
    }

    for (int c = 0; c < NUM_CLASSES; c++) {
        const float* w = WcT + c * DIM;
        float s0 = 0.f, s1 = 0.f, s2 = 0.f, s3 = 0.f;
#pragma unroll
        for (int j = 0; j < 16; j++) {
            float wv = __ldg(&w[j * 32 + lane]);
            s0 += x0[j] * wv; s1 += x1[j] * wv;
            s2 += x2[j] * wv; s3 += x3[j] * wv;
        }
#pragma unroll
        for (int o = 16; o > 0; o >>= 1) {
            s0 += __shfl_xor_sync(0xffffffffu, s0, o);
            s1 += __shfl_xor_sync(0xffffffffu, s1, o);
            s2 += __shfl_xor_sync(0xffffffffu, s2, o);
            s3 += __shfl_xor_sync(0xffffffffu, s3, o);
        }
        if (lane == 0) {
            float b = bc[c];
            out[(size_t)(row0 + 0) * NUM_CLASSES + c] = s0 + b;
            out[(size_t)(row0 + 1) * NUM_CLASSES + c] = s1 + b;
            out[(size_t)(row0 + 2) * NUM_CLASSES + c] = s2 + b;
            out[(size_t)(row0 + 3) * NUM_CLASSES + c] = s3 + b;
        }
    }
}

// ---------------------------------------------------------------------------
extern "C" void kernel_launch(void* const* d_in, const int* in_sizes, int n_in,
                              void* d_out, int out_size) {
    const float* feat = (const float*)d_in[0];
    const int*   src  = (const int*)d_in[1];
    const int*   dst  = (const int*)d_in[2];
    const float* W0 = (const float*)d_in[3];
    const float* b0 = (const float*)d_in[4];
    const float* W1 = (const float*)d_in[5];
    const float* b1 = (const float*)d_in[6];
    const float* W2 = (const float*)d_in[7];
    const float* b2 = (const float*)d_in[8];
    const float* Wc = (const float*)d_in[9];
    const float* bc = (const float*)d_in[10];
    int E = in_sizes[1];

    float4* px;  float4* ph;
    int *pcounts, *poffs, *pcursor, *pesrc;
    float *pWcT, *pWT;
    cudaGetSymbolAddress((void**)&px,      g_x);
    cudaGetSymbolAddress((void**)&ph,      g_h);
    cudaGetSymbolAddress((void**)&pcounts, g_counts);
    cudaGetSymbolAddress((void**)&poffs,   g_offsets);
    cudaGetSymbolAddress((void**)&pcursor, g_cursor);
    cudaGetSymbolAddress((void**)&pesrc,   g_esrc);
    cudaGetSymbolAddress((void**)&pWcT,    g_WcT);
    cudaGetSymbolAddress((void**)&pWT,     g_WT);

    const int GSMEM = 2 * STAGE_FLOATS * (int)sizeof(float);   // 73728 B
    cudaFuncSetAttribute(gemm_mma_kernel,
                         cudaFuncAttributeMaxDynamicSharedMemorySize, GSMEM);

    // CSR build + weight prep
    zero_int_kernel<<<(N_NODES + 1 + 255) / 256, 256>>>(pcounts, N_NODES + 1);
    hist_kernel<<<512, 256>>>(dst, pcounts, E);
    scan_kernel<<<1, 1024>>>(pcounts, poffs, pcursor, N_NODES);
    scatter_kernel<<<512, 256>>>(src, dst, pcursor, pesrc, E);
    transpose_wc_kernel<<<(DIM * NUM_CLASSES + 255) / 256, 256>>>(Wc, pWcT);
    dim3 tgrid(16, 16), tblk(32, 8);
    transpose512_kernel<<<tgrid, tblk>>>(W0, pWT + 0 * DIM * DIM);
    transpose512_kernel<<<tgrid, tblk>>>(W1, pWT + 1 * DIM * DIM);
    transpose512_kernel<<<tgrid, tblk>>>(W2, pWT + 2 * DIM * DIM);

    dim3 ggrid(DIM / 128, (N_NODES + 127) / 128);
    const int ablocks = (N_NODES + 3) / 4;

    const float* lin = feat;
    const float* Ws[3] = {pWT, pWT + DIM * DIM, pWT + 2 * DIM * DIM};
    const float* bs[3] = {b0, b1, b2};
    for (int layer = 0; layer < 3; layer++) {
        for (int t = 0; t < 4; t++)
            agg_tile_kernel<<<ablocks, 128>>>((const float4*)lin, px, poffs, pesrc, t);
        gemm_mma_kernel<<<ggrid, 256, GSMEM>>>((const float*)px, Ws[layer], bs[layer],
                                               (float*)ph, N_NODES);
        lin = (const float*)ph;
    }

    classifier_kernel<<<(N_NODES / 4 * 32 + 255) / 256, 256>>>(
        (const float*)ph, pWcT, bc, (float*)d_out, N_NODES);
}

// round 9
// speedup vs baseline: 2.6611x; 1.4855x over previous
#include <cuda_runtime.h>
#include <cuda_fp16.h>
#include <cuda_bf16.h>
#include <cstdint>
#include <cstring>

// ---------------------------------------------------------------------------
// GIN forward: 3 x (sum-aggregate + Linear(512,512) + ReLU) + Linear(512,40)
// fp16 datapath (fp32 accumulate everywhere):
//  - activations stored fp16 (halves gather + GEMM traffic)
//  - GEMM: mma.sync.m16n8k16.f16.f16.f32 (fast legacy HMMA path)
//  - aggregation: L2-tiled gather, 2 column tiles of 25.6MB
// fp16 mantissa (10 bits) == tf32 mantissa -> same rounding error as before.
// ---------------------------------------------------------------------------

#define N_NODES 50000
#define DIM     512
#define N_EDGES_MAX 400000
#define NUM_CLASSES 40

__device__ __half g_x[N_NODES * DIM];    // aggregated input to Linear (fp16)
__device__ __half g_h[N_NODES * DIM];    // activations / converted feat (fp16)
__device__ int    g_counts[N_NODES + 1];
__device__ int    g_offsets[N_NODES + 1];
__device__ int    g_cursor[N_NODES];
__device__ int    g_esrc[N_EDGES_MAX];
__device__ float  g_WcT[NUM_CLASSES * DIM];
__device__ __half g_WT[3 * DIM * DIM];   // weights [N,K] K-major, fp16

// ------------------------- helpers -----------------------------------------
__device__ __forceinline__ uint32_t h2u(__half2 h) {
    uint32_t u;
    memcpy(&u, &h, 4);
    return u;
}
__device__ __forceinline__ uint32_t smem_u32(const void* p) {
    uint32_t a;
    asm("{ .reg .u64 t; cvta.to.shared.u64 t, %1; cvt.u32.u64 %0, t; }" : "=r"(a) : "l"(p));
    return a;
}
__device__ __forceinline__ void cp16(uint32_t saddr, const void* gaddr, int src_bytes) {
    asm volatile("cp.async.cg.shared.global [%0], [%1], 16, %2;"
                 :: "r"(saddr), "l"(gaddr), "r"(src_bytes) : "memory");
}
__device__ __forceinline__ void cp_commit() {
    asm volatile("cp.async.commit_group;" ::: "memory");
}
template <int N>
__device__ __forceinline__ void cp_wait() {
    asm volatile("cp.async.wait_group %0;" :: "n"(N) : "memory");
}
__device__ __forceinline__ void mma_f16(float c[4], const uint32_t a[4], const uint32_t b[2]) {
    asm volatile(
        "mma.sync.aligned.m16n8k16.row.col.f32.f16.f16.f32 "
        "{%0,%1,%2,%3}, {%4,%5,%6,%7}, {%8,%9}, {%0,%1,%2,%3};"
        : "+f"(c[0]), "+f"(c[1]), "+f"(c[2]), "+f"(c[3])
        : "r"(a[0]), "r"(a[1]), "r"(a[2]), "r"(a[3]), "r"(b[0]), "r"(b[1]));
}

// ------------------------- CSR build ---------------------------------------
__global__ void zero_int_kernel(int* p, int n) {
    int i = blockIdx.x * blockDim.x + threadIdx.x;
    if (i < n) p[i] = 0;
}

__global__ void hist_kernel(const int* __restrict__ dst, int* __restrict__ counts, int E) {
    for (int e = blockIdx.x * blockDim.x + threadIdx.x; e < E; e += gridDim.x * blockDim.x)
        atomicAdd(&counts[dst[e]], 1);
}

__global__ void scan_kernel(const int* __restrict__ counts, int* __restrict__ offs,
                            int* __restrict__ cursor, int n) {
    __shared__ int sums[1024];
    int t = threadIdx.x;
    const int chunk = (n + 1023) / 1024;
    int beg = t * chunk; if (beg > n) beg = n;
    int end = beg + chunk; if (end > n) end = n;
    int s = 0;
    for (int i = beg; i < end; i++) s += counts[i];
    int mys = s;
    sums[t] = s;
    __syncthreads();
    for (int off = 1; off < 1024; off <<= 1) {
        int v = (t >= off) ? sums[t - off] : 0;
        __syncthreads();
        sums[t] += v;
        __syncthreads();
    }
    int run = sums[t] - mys;
    for (int i = beg; i < end; i++) {
        offs[i] = run; cursor[i] = run; run += counts[i];
    }
    if (t == 1023) offs[n] = sums[1023];
}

__global__ void scatter_kernel(const int* __restrict__ src, const int* __restrict__ dst,
                               int* __restrict__ cursor, int* __restrict__ esrc, int E) {
    for (int e = blockIdx.x * blockDim.x + threadIdx.x; e < E; e += gridDim.x * blockDim.x) {
        int pos = atomicAdd(&cursor[dst[e]], 1);
        esrc[pos] = src[e];
    }
}

__global__ void transpose_wc_kernel(const float* __restrict__ Wc, float* __restrict__ WcT) {
    int i = blockIdx.x * blockDim.x + threadIdx.x;
    if (i < DIM * NUM_CLASSES) {
        int k = i / NUM_CLASSES, c = i % NUM_CLASSES;
        WcT[c * DIM + k] = Wc[i];
    }
}

// W [K,N] row-major fp32 -> WT [N,K] row-major fp16
__global__ void transpose512h_kernel(const float* __restrict__ W, __half* __restrict__ WT) {
    __shared__ float t[32][33];
    int bx = blockIdx.x * 32, by = blockIdx.y * 32;
#pragma unroll
    for (int i = 0; i < 32; i += 8)
        t[threadIdx.y + i][threadIdx.x] = W[(by + threadIdx.y + i) * DIM + bx + threadIdx.x];
    __syncthreads();
#pragma unroll
    for (int i = 0; i < 32; i += 8)
        WT[(bx + threadIdx.y + i) * DIM + by + threadIdx.x] =
            __float2half_rn(t[threadIdx.x][threadIdx.y + i]);
}

// fp32 -> fp16 conversion (feat)
__global__ void f2h_kernel(const float4* __restrict__ in, uint2* __restrict__ out, int n4) {
    int i = blockIdx.x * blockDim.x + threadIdx.x;
    if (i < n4) {
        float4 v = in[i];
        uint2 o;
        o.x = h2u(__floats2half2_rn(v.x, v.y));
        o.y = h2u(__floats2half2_rn(v.z, v.w));
        out[i] = o;
    }
}

// ------------------------- L2-tiled aggregation (fp16) ----------------------
// Warp per node; tile = 32 uint4 columns (256 halves). 2 launches cover 512.
// out = fp16(in[node] + sum_e in[esrc[e]]), accumulated in fp32.
__global__ void __launch_bounds__(256)
agg_half_kernel(const uint4* __restrict__ in, uint4* __restrict__ out,
                const int* __restrict__ offs, const int* __restrict__ esrc, int tile) {
    int warp = threadIdx.x >> 5;
    int lane = threadIdx.x & 31;
    int node = blockIdx.x * 8 + warp;
    if (node >= N_NODES) return;
    int col = tile * 32 + lane;            // uint4 column (64 per 512-half row)

    float acc[8];
    {
        uint4 u = in[(size_t)node * 64 + col];
        const __half2* h2 = (const __half2*)&u;
#pragma unroll
        for (int j = 0; j < 4; j++) {
            float2 f = __half22float2(h2[j]);
            acc[2 * j] = f.x; acc[2 * j + 1] = f.y;
        }
    }
    int e = offs[node], end = offs[node + 1];
    for (; e + 1 < end; e += 2) {
        int s0 = __ldg(&esrc[e]);
        int s1 = __ldg(&esrc[e + 1]);
        uint4 u0 = in[(size_t)s0 * 64 + col];
        uint4 u1 = in[(size_t)s1 * 64 + col];
        const __half2* a2 = (const __half2*)&u0;
        const __half2* b2 = (const __half2*)&u1;
#pragma unroll
        for (int j = 0; j < 4; j++) {
            float2 fa = __half22float2(a2[j]);
            float2 fb = __half22float2(b2[j]);
            acc[2 * j] += fa.x + fb.x;
            acc[2 * j + 1] += fa.y + fb.y;
        }
    }
    if (e < end) {
        int s0 = __ldg(&esrc[e]);
        uint4 u0 = in[(size_t)s0 * 64 + col];
        const __half2* a2 = (const __half2*)&u0;
#pragma unroll
        for (int j = 0; j < 4; j++) {
            float2 fa = __half22float2(a2[j]);
            acc[2 * j] += fa.x;
            acc[2 * j + 1] += fa.y;
        }
    }
    uint4 o;
    o.x = h2u(__floats2half2_rn(acc[0], acc[1]));
    o.y = h2u(__floats2half2_rn(acc[2], acc[3]));
    o.z = h2u(__floats2half2_rn(acc[4], acc[5]));
    o.w = h2u(__floats2half2_rn(acc[6], acc[7]));
    out[(size_t)node * 64 + col] = o;
}

// ------------------------- fp16 mma.sync GEMM (cp.async) --------------------
#define STRH 40                          // SMEM row stride in halves (conflict-free)
#define TILE_HALF (128 * STRH)           // one operand tile (halves)
#define STAGE_HALF (2 * TILE_HALF)       // A + B

// C[M,512] = fp16(relu(A @ WT^T + bias)); A,WT fp16, accumulate fp32.
// CTA 128x128, 8 warps (4 M x 2 N), warptile 32x64, K-chunks 32, 2 stages.
__global__ void __launch_bounds__(256)
gemm_h_kernel(const __half* __restrict__ A, const __half* __restrict__ BT,
              const float* __restrict__ bias, __half* __restrict__ C, int M) {
    __shared__ __half sm[2 * STAGE_HALF];   // 40 KB

    int tid = threadIdx.x;
    int lane = tid & 31, wid = tid >> 5;
    int warpM = wid & 3, warpN = wid >> 2;
    int gid = lane >> 2, tig = lane & 3;
    int rowBase = blockIdx.y * 128;
    int colBase = blockIdx.x * 128;

    // cp.async mapping: thread -> (row = tid>>1, 16-half piece = tid&1)
    int lrow = tid >> 1;
    int hh = tid & 1;
    const __half* Aptr = A + (size_t)(rowBase + lrow) * DIM + hh * 16;
    const __half* Bptr = BT + (size_t)(colBase + lrow) * DIM + hh * 16;
    int a_bytes = ((rowBase + lrow) < M) ? 16 : 0;

    uint32_t smem_base = smem_u32(sm);
    uint32_t sA_st = smem_base + (lrow * STRH + hh * 16) * 2;
    uint32_t sB_st = sA_st + TILE_HALF * 2;

    float acc[2][8][4];
#pragma unroll
    for (int mt = 0; mt < 2; mt++)
#pragma unroll
        for (int nt = 0; nt < 8; nt++)
#pragma unroll
            for (int c = 0; c < 4; c++) acc[mt][nt][c] = 0.f;

    // prologue: stage 0 (k0 = 0)
#pragma unroll
    for (int i = 0; i < 2; i++) {
        cp16(sA_st + i * 16, Aptr + i * 8, a_bytes);
        cp16(sB_st + i * 16, Bptr + i * 8, 16);
    }
    cp_commit();

    for (int kt = 0; kt < 16; kt++) {
        if (kt < 15) {
            int k0 = (kt + 1) * 32;
            uint32_t off = ((kt + 1) & 1) * STAGE_HALF * 2;
#pragma unroll
            for (int i = 0; i < 2; i++) {
                cp16(sA_st + off + i * 16, Aptr + k0 + i * 8, a_bytes);
                cp16(sB_st + off + i * 16, Bptr + k0 + i * 8, 16);
            }
            cp_commit();
            cp_wait<1>();
        } else {
            cp_wait<0>();
        }
        __syncthreads();

        const __half* sA = sm + (kt & 1) * STAGE_HALF;
        const __half* sB = sA + TILE_HALF;
#pragma unroll
        for (int ks = 0; ks < 2; ks++) {           // two k16 steps per 32-chunk
            int kb = ks * 16;
            uint32_t af[2][4];
#pragma unroll
            for (int mt = 0; mt < 2; mt++) {
                int mrow = warpM * 32 + mt * 16 + gid;
                af[mt][0] = *(const uint32_t*)(sA + mrow * STRH + kb + 2 * tig);
                af[mt][1] = *(const uint32_t*)(sA + (mrow + 8) * STRH + kb + 2 * tig);
                af[mt][2] = *(const uint32_t*)(sA + mrow * STRH + kb + 2 * tig + 8);
                af[mt][3] = *(const uint32_t*)(sA + (mrow + 8) * STRH + kb + 2 * tig + 8);
            }
            uint32_t bf[8][2];
#pragma unroll
            for (int nt = 0; nt < 8; nt++) {
                int ncol = warpN * 64 + nt * 8 + gid;
                bf[nt][0] = *(const uint32_t*)(sB + ncol * STRH + kb + 2 * tig);
                bf[nt][1] = *(const uint32_t*)(sB + ncol * STRH + kb + 2 * tig + 8);
            }
#pragma unroll
            for (int mt = 0; mt < 2; mt++)
#pragma unroll
                for (int nt = 0; nt < 8; nt++)
                    mma_f16(acc[mt][nt], af[mt], bf[nt]);
        }
        __syncthreads();
    }

    // Epilogue: bias + relu, store fp16 (half2 per c-pair)
#pragma unroll
    for (int mt = 0; mt < 2; mt++) {
        int r0 = rowBase + warpM * 32 + mt * 16 + gid;
        int r1 = r0 + 8;
#pragma unroll
        for (int nt = 0; nt < 8; nt++) {
            int col = colBase + warpN * 64 + nt * 8 + 2 * tig;
            float bx = bias[col], by = bias[col + 1];
            if (r0 < M) {
                __half2 v = __floats2half2_rn(fmaxf(acc[mt][nt][0] + bx, 0.f),
                                              fmaxf(acc[mt][nt][1] + by, 0.f));
                *(__half2*)(C + (size_t)r0 * DIM + col) = v;
            }
            if (r1 < M) {
                __half2 v = __floats2half2_rn(fmaxf(acc[mt][nt][2] + bx, 0.f),
                                              fmaxf(acc[mt][nt][3] + by, 0.f));
                *(__half2*)(C + (size_t)r1 * DIM + col) = v;
            }
        }
    }
}

// ------------------------- classifier (fp16 X) ------------------------------
__global__ void __launch_bounds__(256)
classifier_kernel(const __half* __restrict__ X, const float* __restrict__ WcT,
                  const float* __restrict__ bc, float* __restrict__ out, int M) {
    int warp = (blockIdx.x * blockDim.x + threadIdx.x) >> 5;
    int lane = threadIdx.x & 31;
    int row0 = warp * 4;
    if (row0 >= M) return;

    float x0[16], x1[16], x2[16], x3[16];
    const __half* X0 = X + (size_t)row0 * DIM;
#pragma unroll
    for (int j = 0; j < 16; j++) {
        int k = j * 32 + lane;
        x0[j] = __half2float(X0[k]);
        x1[j] = __half2float(X0[DIM + k]);
        x2[j] = __half2float(X0[2 * DIM + k]);
        x3[j] = __half2float(X0[3 * DIM + k]);
    }

    for (int c = 0; c < NUM_CLASSES; c++) {
        const float* w = WcT + c * DIM;
        float s0 = 0.f, s1 = 0.f, s2 = 0.f, s3 = 0.f;
#pragma unroll
        for (int j = 0; j < 16; j++) {
            float wv = __ldg(&w[j * 32 + lane]);
            s0 += x0[j] * wv; s1 += x1[j] * wv;
            s2 += x2[j] * wv; s3 += x3[j] * wv;
        }
#pragma unroll
        for (int o = 16; o > 0; o >>= 1) {
            s0 += __shfl_xor_sync(0xffffffffu, s0, o);
            s1 += __shfl_xor_sync(0xffffffffu, s1, o);
            s2 += __shfl_xor_sync(0xffffffffu, s2, o);
            s3 += __shfl_xor_sync(0xffffffffu, s3, o);
        }
        if (lane == 0) {
            float b = bc[c];
            out[(size_t)(row0 + 0) * NUM_CLASSES + c] = s0 + b;
            out[(size_t)(row0 + 1) * NUM_CLASSES + c] = s1 + b;
            out[(size_t)(row0 + 2) * NUM_CLASSES + c] = s2 + b;
            out[(size_t)(row0 + 3) * NUM_CLASSES + c] = s3 + b;
        }
    }
}

// ---------------------------------------------------------------------------
extern "C" void kernel_launch(void* const* d_in, const int* in_sizes, int n_in,
                              void* d_out, int out_size) {
    const float* feat = (const float*)d_in[0];
    const int*   src  = (const int*)d_in[1];
    const int*   dst  = (const int*)d_in[2];
    const float* W0 = (const float*)d_in[3];
    const float* b0 = (const float*)d_in[4];
    const float* W1 = (const float*)d_in[5];
    const float* b1 = (const float*)d_in[6];
    const float* W2 = (const float*)d_in[7];
    const float* b2 = (const float*)d_in[8];
    const float* Wc = (const float*)d_in[9];
    const float* bc = (const float*)d_in[10];
    int E = in_sizes[1];

    __half *px, *ph, *pWT;
    int *pcounts, *poffs, *pcursor, *pesrc;
    float *pWcT;
    cudaGetSymbolAddress((void**)&px,      g_x);
    cudaGetSymbolAddress((void**)&ph,      g_h);
    cudaGetSymbolAddress((void**)&pcounts, g_counts);
    cudaGetSymbolAddress((void**)&poffs,   g_offsets);
    cudaGetSymbolAddress((void**)&pcursor, g_cursor);
    cudaGetSymbolAddress((void**)&pesrc,   g_esrc);
    cudaGetSymbolAddress((void**)&pWcT,    g_WcT);
    cudaGetSymbolAddress((void**)&pWT,     g_WT);

    // CSR build + weight prep + feat conversion
    zero_int_kernel<<<(N_NODES + 1 + 255) / 256, 256>>>(pcounts, N_NODES + 1);
    hist_kernel<<<512, 256>>>(dst, pcounts, E);
    scan_kernel<<<1, 1024>>>(pcounts, poffs, pcursor, N_NODES);
    scatter_kernel<<<512, 256>>>(src, dst, pcursor, pesrc, E);
    transpose_wc_kernel<<<(DIM * NUM_CLASSES + 255) / 256, 256>>>(Wc, pWcT);
    dim3 tgrid(16, 16), tblk(32, 8);
    transpose512h_kernel<<<tgrid, tblk>>>(W0, pWT + 0 * DIM * DIM);
    transpose512h_kernel<<<tgrid, tblk>>>(W1, pWT + 1 * DIM * DIM);
    transpose512h_kernel<<<tgrid, tblk>>>(W2, pWT + 2 * DIM * DIM);
    const int n4 = N_NODES * DIM / 4;
    f2h_kernel<<<(n4 + 255) / 256, 256>>>((const float4*)feat, (uint2*)ph, n4);

    dim3 ggrid(DIM / 128, (N_NODES + 127) / 128);
    const int ablocks = (N_NODES + 7) / 8;

    const __half* Ws[3] = {pWT, pWT + DIM * DIM, pWT + 2 * DIM * DIM};
    const float* bs[3] = {b0, b1, b2};
    for (int layer = 0; layer < 3; layer++) {
        for (int t = 0; t < 2; t++)
            agg_half_kernel<<<ablocks, 256>>>((const uint4*)ph, (uint4*)px, poffs, pesrc, t);
        gemm_h_kernel<<<ggrid, 256>>>(px, Ws[layer], bs[layer], ph, N_NODES);
    }

    classifier_kernel<<<(N_NODES / 4 * 32 + 255) / 256, 256>>>(
        ph, pWcT, bc, (float*)d_out, N_NODES);
}

// round 12
// speedup vs baseline: 2.7935x; 1.0497x over previous
#include <cuda_runtime.h>
#include <cuda_fp16.h>
#include <cuda_bf16.h>
#include <cstdint>
#include <cstring>

// ---------------------------------------------------------------------------
// GIN forward: 3 x (sum-aggregate + Linear(512,512) + ReLU) + Linear(512,40)
// fp16 datapath, fp32 accumulate.
//  - GEMM: mma.sync.m16n8k16 + ldmatrix fragment loads (4x fewer shared ops)
//  - aggregation: single-pass full-row gather (51MB slice, L2-resident)
// ---------------------------------------------------------------------------

#define N_NODES 50000
#define DIM     512
#define N_EDGES_MAX 400000
#define NUM_CLASSES 40

__device__ __half g_x[N_NODES * DIM];
__device__ __half g_h[N_NODES * DIM];
__device__ int    g_counts[N_NODES + 1];
__device__ int    g_offsets[N_NODES + 1];
__device__ int    g_cursor[N_NODES];
__device__ int    g_esrc[N_EDGES_MAX];
__device__ float  g_WcT[NUM_CLASSES * DIM];
__device__ __half g_WT[3 * DIM * DIM];   // weights [N,K] K-major, fp16

// ------------------------- helpers -----------------------------------------
__device__ __forceinline__ uint32_t h2u(__half2 h) {
    uint32_t u;
    memcpy(&u, &h, 4);
    return u;
}
__device__ __forceinline__ uint32_t smem_u32(const void* p) {
    uint32_t a;
    asm("{ .reg .u64 t; cvta.to.shared.u64 t, %1; cvt.u32.u64 %0, t; }" : "=r"(a) : "l"(p));
    return a;
}
__device__ __forceinline__ void cp16(uint32_t saddr, const void* gaddr, int src_bytes) {
    asm volatile("cp.async.cg.shared.global [%0], [%1], 16, %2;"
                 :: "r"(saddr), "l"(gaddr), "r"(src_bytes) : "memory");
}
__device__ __forceinline__ void cp_commit() {
    asm volatile("cp.async.commit_group;" ::: "memory");
}
template <int N>
__device__ __forceinline__ void cp_wait() {
    asm volatile("cp.async.wait_group %0;" :: "n"(N) : "memory");
}
__device__ __forceinline__ void ldsm_x4(uint32_t r[4], uint32_t saddr) {
    asm volatile("ldmatrix.sync.aligned.m8n8.x4.shared.b16 {%0,%1,%2,%3}, [%4];"
                 : "=r"(r[0]), "=r"(r[1]), "=r"(r[2]), "=r"(r[3]) : "r"(saddr));
}
__device__ __forceinline__ void mma_f16(float c[4], const uint32_t a[4], const uint32_t b[2]) {
    asm volatile(
        "mma.sync.aligned.m16n8k16.row.col.f32.f16.f16.f32 "
        "{%0,%1,%2,%3}, {%4,%5,%6,%7}, {%8,%9}, {%0,%1,%2,%3};"
        : "+f"(c[0]), "+f"(c[1]), "+f"(c[2]), "+f"(c[3])
        : "r"(a[0]), "r"(a[1]), "r"(a[2]), "r"(a[3]), "r"(b[0]), "r"(b[1]));
}

// ------------------------- CSR build ---------------------------------------
__global__ void zero_int_kernel(int* p, int n) {
    int i = blockIdx.x * blockDim.x + threadIdx.x;
    if (i < n) p[i] = 0;
}

__global__ void hist_kernel(const int* __restrict__ dst, int* __restrict__ counts, int E) {
    for (int e = blockIdx.x * blockDim.x + threadIdx.x; e < E; e += gridDim.x * blockDim.x)
        atomicAdd(&counts[dst[e]], 1);
}

__global__ void scan_kernel(const int* __restrict__ counts, int* __restrict__ offs,
                            int* __restrict__ cursor, int n) {
    __shared__ int sums[1024];
    int t = threadIdx.x;
    const int chunk = (n + 1023) / 1024;
    int beg = t * chunk; if (beg > n) beg = n;
    int end = beg + chunk; if (end > n) end = n;
    int s = 0;
    for (int i = beg; i < end; i++) s += counts[i];
    int mys = s;
    sums[t] = s;
    __syncthreads();
    for (int off = 1; off < 1024; off <<= 1) {
        int v = (t >= off) ? sums[t - off] : 0;
        __syncthreads();
        sums[t] += v;
        __syncthreads();
    }
    int run = sums[t] - mys;
    for (int i = beg; i < end; i++) {
        offs[i] = run; cursor[i] = run; run += counts[i];
    }
    if (t == 1023) offs[n] = sums[1023];
}

__global__ void scatter_kernel(const int* __restrict__ src, const int* __restrict__ dst,
                               int* __restrict__ cursor, int* __restrict__ esrc, int E) {
    for (int e = blockIdx.x * blockDim.x + threadIdx.x; e < E; e += gridDim.x * blockDim.x) {
        int pos = atomicAdd(&cursor[dst[e]], 1);
        esrc[pos] = src[e];
    }
}

__global__ void transpose_wc_kernel(const float* __restrict__ Wc, float* __restrict__ WcT) {
    int i = blockIdx.x * blockDim.x + threadIdx.x;
    if (i < DIM * NUM_CLASSES) {
        int k = i / NUM_CLASSES, c = i % NUM_CLASSES;
        WcT[c * DIM + k] = Wc[i];
    }
}

// W [K,N] row-major fp32 -> WT [N,K] row-major fp16
__global__ void transpose512h_kernel(const float* __restrict__ W, __half* __restrict__ WT) {
    __shared__ float t[32][33];
    int bx = blockIdx.x * 32, by = blockIdx.y * 32;
#pragma unroll
    for (int i = 0; i < 32; i += 8)
        t[threadIdx.y + i][threadIdx.x] = W[(by + threadIdx.y + i) * DIM + bx + threadIdx.x];
    __syncthreads();
#pragma unroll
    for (int i = 0; i < 32; i += 8)
        WT[(bx + threadIdx.y + i) * DIM + by + threadIdx.x] =
            __float2half_rn(t[threadIdx.x][threadIdx.y + i]);
}

// fp32 -> fp16 conversion (feat)
__global__ void f2h_kernel(const float4* __restrict__ in, uint2* __restrict__ out, int n4) {
    int i = blockIdx.x * blockDim.x + threadIdx.x;
    if (i < n4) {
        float4 v = in[i];
        uint2 o;
        o.x = h2u(__floats2half2_rn(v.x, v.y));
        o.y = h2u(__floats2half2_rn(v.z, v.w));
        out[i] = o;
    }
}

// ------------------------- aggregation (fp16, single pass) ------------------
// Warp per node; lane covers uint4 columns {lane, lane+32} of the 64-uint4 row.
// out = fp16(in[node] + sum_e in[esrc[e]]), accumulated in fp32.
__global__ void __launch_bounds__(256)
agg_half_kernel(const uint4* __restrict__ in, uint4* __restrict__ out,
                const int* __restrict__ offs, const int* __restrict__ esrc) {
    int warp = threadIdx.x >> 5;
    int lane = threadIdx.x & 31;
    int node = blockIdx.x * 8 + warp;
    if (node >= N_NODES) return;

    float acc[16];
#pragma unroll
    for (int p = 0; p < 2; p++) {
        uint4 u = in[(size_t)node * 64 + lane + p * 32];
        const __half2* h2 = (const __half2*)&u;
#pragma unroll
        for (int j = 0; j < 4; j++) {
            float2 f = __half22float2(h2[j]);
            acc[p * 8 + 2 * j] = f.x; acc[p * 8 + 2 * j + 1] = f.y;
        }
    }
    int e = offs[node], end = offs[node + 1];
    for (; e + 1 < end; e += 2) {
        int s0 = __ldg(&esrc[e]);
        int s1 = __ldg(&esrc[e + 1]);
#pragma unroll
        for (int p = 0; p < 2; p++) {
            uint4 u0 = in[(size_t)s0 * 64 + lane + p * 32];
            uint4 u1 = in[(size_t)s1 * 64 + lane + p * 32];
            const __half2* a2 = (const __half2*)&u0;
            const __half2* b2 = (const __half2*)&u1;
#pragma unroll
            for (int j = 0; j < 4; j++) {
                float2 fa = __half22float2(a2[j]);
                float2 fb = __half22float2(b2[j]);
                acc[p * 8 + 2 * j] += fa.x + fb.x;
                acc[p * 8 + 2 * j + 1] += fa.y + fb.y;
            }
        }
    }
    if (e < end) {
        int s0 = __ldg(&esrc[e]);
#pragma unroll
        for (int p = 0; p < 2; p++) {
            uint4 u0 = in[(size_t)s0 * 64 + lane + p * 32];
            const __half2* a2 = (const __half2*)&u0;
#pragma unroll
            for (int j = 0; j < 4; j++) {
                float2 fa = __half22float2(a2[j]);
                acc[p * 8 + 2 * j] += fa.x;
                acc[p * 8 + 2 * j + 1] += fa.y;
            }
        }
    }
#pragma unroll
    for (int p = 0; p < 2; p++) {
        uint4 o;
        o.x = h2u(__floats2half2_rn(acc[p * 8 + 0], acc[p * 8 + 1]));
        o.y = h2u(__floats2half2_rn(acc[p * 8 + 2], acc[p * 8 + 3]));
        o.z = h2u(__floats2half2_rn(acc[p * 8 + 4], acc[p * 8 + 5]));
        o.w = h2u(__floats2half2_rn(acc[p * 8 + 6], acc[p * 8 + 7]));
        out[(size_t)node * 64 + lane + p * 32] = o;
    }
}

// ------------------------- fp16 mma.sync GEMM (cp.async + ldmatrix) ---------
#define STRH 40                          // SMEM row stride in halves
#define TILE_HALF (128 * STRH)
#define STAGE_HALF (2 * TILE_HALF)

// C[M,512] = fp16(relu(A @ WT^T + bias)); CTA 128x128, 8 warps (4Mx2N),
// warptile 32x64, K-chunks 32, 2 stages, ldmatrix fragment loads.
__global__ void __launch_bounds__(256)
gemm_h_kernel(const __half* __restrict__ A, const __half* __restrict__ BT,
              const float* __restrict__ bias, __half* __restrict__ C, int M) {
    __shared__ __half sm[2 * STAGE_HALF];   // 40 KB

    int tid = threadIdx.x;
    int lane = tid & 31, wid = tid >> 5;
    int warpM = wid & 3, warpN = wid >> 2;
    int gid = lane >> 2, tig = lane & 3;
    int rowBase = blockIdx.y * 128;
    int colBase = blockIdx.x * 128;

    // cp.async mapping
    int lrow = tid >> 1;
    int hh = tid & 1;
    const __half* Aptr = A + (size_t)(rowBase + lrow) * DIM + hh * 16;
    const __half* Bptr = BT + (size_t)(colBase + lrow) * DIM + hh * 16;
    int a_bytes = ((rowBase + lrow) < M) ? 16 : 0;

    uint32_t smem_base = smem_u32(sm);
    uint32_t sA_st = smem_base + (lrow * STRH + hh * 16) * 2;
    uint32_t sB_st = sA_st + TILE_HALF * 2;

    // ldmatrix lane-address components (halves)
    // A: row = warpM*32 + mt*16 + (lane&15); col = ks*16 + (lane>>4)*8
    int a_row = warpM * 32 + (lane & 15);
    int a_col = (lane >> 4) << 3;
    // B: row = warpN*64 + np*16 + (lane&7) + ((lane>>4)<<3); col = ks*16 + ((lane>>3)&1)*8
    int b_row = warpN * 64 + (lane & 7) + ((lane >> 4) << 3);
    int b_col = ((lane >> 3) & 1) << 3;

    float acc[2][8][4];
#pragma unroll
    for (int mt = 0; mt < 2; mt++)
#pragma unroll
        for (int nt = 0; nt < 8; nt++)
#pragma unroll
            for (int c = 0; c < 4; c++) acc[mt][nt][c] = 0.f;

    // prologue
#pragma unroll
    for (int i = 0; i < 2; i++) {
        cp16(sA_st + i * 16, Aptr + i * 8, a_bytes);
        cp16(sB_st + i * 16, Bptr + i * 8, 16);
    }
    cp_commit();

    for (int kt = 0; kt < 16; kt++) {
        if (kt < 15) {
            int k0 = (kt + 1) * 32;
            uint32_t off = ((kt + 1) & 1) * STAGE_HALF * 2;
#pragma unroll
            for (int i = 0; i < 2; i++) {
                cp16(sA_st + off + i * 16, Aptr + k0 + i * 8, a_bytes);
                cp16(sB_st + off + i * 16, Bptr + k0 + i * 8, 16);
            }
            cp_commit();
            cp_wait<1>();
        } else {
            cp_wait<0>();
        }
        __syncthreads();

        uint32_t sA = smem_base + (kt & 1) * STAGE_HALF * 2;
        uint32_t sB = sA + TILE_HALF * 2;
#pragma unroll
        for (int ks = 0; ks < 2; ks++) {
            int kb = ks * 16;
            uint32_t af[2][4];
#pragma unroll
            for (int mt = 0; mt < 2; mt++)
                ldsm_x4(af[mt], sA + ((a_row + mt * 16) * STRH + kb + a_col) * 2);
            uint32_t bf[8][2];
#pragma unroll
            for (int np = 0; np < 4; np++) {
                uint32_t t4[4];
                ldsm_x4(t4, sB + ((b_row + np * 16) * STRH + kb + b_col) * 2);
                bf[2 * np][0] = t4[0]; bf[2 * np][1] = t4[1];
                bf[2 * np + 1][0] = t4[2]; bf[2 * np + 1][1] = t4[3];
            }
#pragma unroll
            for (int mt = 0; mt < 2; mt++)
#pragma unroll
                for (int nt = 0; nt < 8; nt++)
                    mma_f16(acc[mt][nt], af[mt], bf[nt]);
        }
        __syncthreads();
    }

    // Epilogue: bias + relu, store fp16
#pragma unroll
    for (int mt = 0; mt < 2; mt++) {
        int r0 = rowBase + warpM * 32 + mt * 16 + gid;
        int r1 = r0 + 8;
#pragma unroll
        for (int nt = 0; nt < 8; nt++) {
            int col = colBase + warpN * 64 + nt * 8 + 2 * tig;
            float bx = bias[col], by = bias[col + 1];
            if (r0 < M) {
                __half2 v = __floats2half2_rn(fmaxf(acc[mt][nt][0] + bx, 0.f),
                                              fmaxf(acc[mt][nt][1] + by, 0.f));
                *(__half2*)(C + (size_t)r0 * DIM + col) = v;
            }
            if (r1 < M) {
                __half2 v = __floats2half2_rn(fmaxf(acc[mt][nt][2] + bx, 0.f),
                                              fmaxf(acc[mt][nt][3] + by, 0.f));
                *(__half2*)(C + (size_t)r1 * DIM + col) = v;
            }
        }
    }
}

// ------------------------- classifier (fp16 X) ------------------------------
__global__ void __launch_bounds__(256)
classifier_kernel(const __half* __restrict__ X, const float* __restrict__ WcT,
                  const float* __restrict__ bc, float* __restrict__ out, int M) {
    int warp = (blockIdx.x * blockDim.x + threadIdx.x) >> 5;
    int lane = threadIdx.x & 31;
    int row0 = warp * 4;
    if (row0 >= M) return;

    float x0[16], x1[16], x2[16], x3[16];
    const __half* X0 = X + (size_t)row0 * DIM;
#pragma unroll
    for (int j = 0; j < 16; j++) {
        int k = j * 32 + lane;
        x0[j] = __half2float(X0[k]);
        x1[j] = __half2float(X0[DIM + k]);
        x2[j] = __half2float(X0[2 * DIM + k]);
        x3[j] = __half2float(X0[3 * DIM + k]);
    }

    for (int c = 0; c < NUM_CLASSES; c++) {
        const float* w = WcT + c * DIM;
        float s0 = 0.f, s1 = 0.f, s2 = 0.f, s3 = 0.f;
#pragma unroll
        for (int j = 0; j < 16; j++) {
            float wv = __ldg(&w[j * 32 + lane]);
            s0 += x0[j] * wv; s1 += x1[j] * wv;
            s2 += x2[j] * wv; s3 += x3[j] * wv;
        }
#pragma unroll
        for (int o = 16; o > 0; o >>= 1) {
            s0 += __shfl_xor_sync(0xffffffffu, s0, o);
            s1 += __shfl_xor_sync(0xffffffffu, s1, o);
            s2 += __shfl_xor_sync(0xffffffffu, s2, o);
            s3 += __shfl_xor_sync(0xffffffffu, s3, o);
        }
        if (lane == 0) {
            float b = bc[c];
            out[(size_t)(row0 + 0) * NUM_CLASSES + c] = s0 + b;
            out[(size_t)(row0 + 1) * NUM_CLASSES + c] = s1 + b;
            out[(size_t)(row0 + 2) * NUM_CLASSES + c] = s2 + b;
            out[(size_t)(row0 + 3) * NUM_CLASSES + c] = s3 + b;
        }
    }
}

// ---------------------------------------------------------------------------
extern "C" void kernel_launch(void* const* d_in, const int* in_sizes, int n_in,
                              void* d_out, int out_size) {
    const float* feat = (const float*)d_in[0];
    const int*   src  = (const int*)d_in[1];
    const int*   dst  = (const int*)d_in[2];
    const float* W0 = (const float*)d_in[3];
    const float* b0 = (const float*)d_in[4];
    const float* W1 = (const float*)d_in[5];
    const float* b1 = (const float*)d_in[6];
    const float* W2 = (const float*)d_in[7];
    const float* b2 = (const float*)d_in[8];
    const float* Wc = (const float*)d_in[9];
    const float* bc = (const float*)d_in[10];
    int E = in_sizes[1];

    __half *px, *ph, *pWT;
    int *pcounts, *poffs, *pcursor, *pesrc;
    float *pWcT;
    cudaGetSymbolAddress((void**)&px,      g_x);
    cudaGetSymbolAddress((void**)&ph,      g_h);
    cudaGetSymbolAddress((void**)&pcounts, g_counts);
    cudaGetSymbolAddress((void**)&poffs,   g_offsets);
    cudaGetSymbolAddress((void**)&pcursor, g_cursor);
    cudaGetSymbolAddress((void**)&pesrc,   g_esrc);
    cudaGetSymbolAddress((void**)&pWcT,    g_WcT);
    cudaGetSymbolAddress((void**)&pWT,     g_WT);

    // CSR build + weight prep + feat conversion
    zero_int_kernel<<<(N_NODES + 1 + 255) / 256, 256>>>(pcounts, N_NODES + 1);
    hist_kernel<<<512, 256>>>(dst, pcounts, E);
    scan_kernel<<<1, 1024>>>(pcounts, poffs, pcursor, N_NODES);
    scatter_kernel<<<512, 256>>>(src, dst, pcursor, pesrc, E);
    transpose_wc_kernel<<<(DIM * NUM_CLASSES + 255) / 256, 256>>>(Wc, pWcT);
    dim3 tgrid(16, 16), tblk(32, 8);
    transpose512h_kernel<<<tgrid, tblk>>>(W0, pWT + 0 * DIM * DIM);
    transpose512h_kernel<<<tgrid, tblk>>>(W1, pWT + 1 * DIM * DIM);
    transpose512h_kernel<<<tgrid, tblk>>>(W2, pWT + 2 * DIM * DIM);
    const int n4 = N_NODES * DIM / 4;
    f2h_kernel<<<(n4 + 255) / 256, 256>>>((const float4*)feat, (uint2*)ph, n4);

    dim3 ggrid(DIM / 128, (N_NODES + 127) / 128);
    const int ablocks = (N_NODES + 7) / 8;

    const __half* Ws[3] = {pWT, pWT + DIM * DIM, pWT + 2 * DIM * DIM};
    const float* bs[3] = {b0, b1, b2};
    for (int layer = 0; layer < 3; layer++) {
        agg_half_kernel<<<ablocks, 256>>>((const uint4*)ph, (uint4*)px, poffs, pesrc);
        gemm_h_kernel<<<ggrid, 256>>>(px, Ws[layer], bs[layer], ph, N_NODES);
    }

    classifier_kernel<<<(N_NODES / 4 * 32 + 255) / 256, 256>>>(
        ph, pWcT, bc, (float*)d_out, N_NODES);
}